// round 1
// baseline (speedup 1.0000x reference)
#include <cuda_runtime.h>
#include <stdint.h>

// Problem constants (fixed by reference)
#define NN   20000              // nodes
#define RR   11                 // relations
#define BB   8                  // bases
#define IND  300                // in dim
#define OUTD 256                // out dim
#define EE   640000             // edges
#define KK   (BB*IND)           // 2400 = GEMM K

// -------- device scratch (no dynamic allocation allowed) --------
__device__ int   g_deg[RR*NN];        // per (rel,src) degree
__device__ int   g_cnt[NN];           // per-src edge count
__device__ int   g_off[NN+1];         // CSR offsets
__device__ int   g_cur[NN];           // scatter cursors
__device__ uint2 g_edges[EE];         // packed (dst | rel<<16, val)
__device__ float g_H[(size_t)NN*KK];  // aggregated basis-space features, 192 MB

// -------- 0: reset counters (must be idempotent per graph replay) --------
__global__ void k_zero() {
    int i  = blockIdx.x * blockDim.x + threadIdx.x;
    int st = gridDim.x * blockDim.x;
    for (int j = i; j < RR*NN; j += st) g_deg[j] = 0;
    for (int j = i; j < NN;    j += st) g_cnt[j] = 0;
}

// -------- 1: histogram degrees --------
__global__ void k_count(const int* __restrict__ src, const int* __restrict__ rel, int E) {
    int e = blockIdx.x * blockDim.x + threadIdx.x;
    if (e < E) {
        int s = src[e], r = rel[e];
        atomicAdd(&g_deg[r*NN + s], 1);
        atomicAdd(&g_cnt[s], 1);
    }
}

// -------- 2: exclusive scan over 20000 src counts (single block) --------
__global__ void k_scan() {
    __shared__ int sh[1024];
    int t = threadIdx.x;
    const int C = (NN + 1023) / 1024;   // 20
    int base = t * C;
    int sum = 0;
    for (int j = 0; j < C; j++) { int idx = base + j; if (idx < NN) sum += g_cnt[idx]; }
    sh[t] = sum; __syncthreads();
    for (int d = 1; d < 1024; d <<= 1) {
        int v = (t >= d) ? sh[t-d] : 0;
        __syncthreads();
        sh[t] += v;
        __syncthreads();
    }
    int run = (t > 0) ? sh[t-1] : 0;
    for (int j = 0; j < C; j++) {
        int idx = base + j;
        if (idx < NN) { g_off[idx] = run; g_cur[idx] = run; run += g_cnt[idx]; }
    }
    if (t == 1023) g_off[NN] = sh[1023];
}

// -------- 3: scatter edges into CSR, fold in 1/deg --------
__global__ void k_scatter(const int* __restrict__ src, const int* __restrict__ rel,
                          const int* __restrict__ dst, int E) {
    int e = blockIdx.x * blockDim.x + threadIdx.x;
    if (e < E) {
        int s = src[e], r = rel[e], d = dst[e];
        int pos = atomicAdd(&g_cur[s], 1);
        float val = 1.0f / (float)g_deg[r*NN + s];
        g_edges[pos] = make_uint2((unsigned)(d | (r << 16)), __float_as_uint(val));
    }
}

// -------- 4: per-node gather into basis space: H[n, b*300+i] --------
__global__ void __launch_bounds__(256) k_gather(const float* __restrict__ feat,
                                                const float* __restrict__ comps) {
    __shared__ float s_comps[RR*BB];
    __shared__ uint2 s_ent[64];
    int n = blockIdx.x, t = threadIdx.x;
    if (t < RR*BB) s_comps[t] = comps[t];
    int beg = g_off[n], end = g_off[n+1];
    bool has2 = (t + 256) < IND;          // threads 0..43 own a 2nd feature slot
    float a0[BB], a1[BB];
#pragma unroll
    for (int b = 0; b < BB; b++) { a0[b] = 0.f; a1[b] = 0.f; }
    __syncthreads();

    for (int base = beg; base < end; base += 64) {
        int m = min(64, end - base);
        if (t < m) s_ent[t] = g_edges[base + t];
        __syncthreads();
        for (int j = 0; j < m; j++) {
            uint2 ent = s_ent[j];
            int d = ent.x & 0xFFFF;
            int r = ent.x >> 16;
            float val = __uint_as_float(ent.y);
            const float* f = feat + (size_t)d * IND;
            float f0 = f[t];
            float f1 = has2 ? f[t + 256] : 0.f;
            const float* cp = &s_comps[r*BB];
#pragma unroll
            for (int b = 0; b < BB; b++) {
                float c = val * cp[b];
                a0[b] += c * f0;
                a1[b] += c * f1;
            }
        }
        __syncthreads();
    }

    float* h = g_H + (size_t)n * KK;
#pragma unroll
    for (int b = 0; b < BB; b++) {
        h[b*IND + t] = a0[b];
        if (has2) h[b*IND + 256 + t] = a1[b];
    }
}

// -------- 5: SGEMM  out[20000,256] = H[20000,2400] @ basesFlat[2400,256] + bias --------
// BM=128, BN=64, BK=8, 128 threads, 8x8 per-thread tile, reg-prefetch double stage.
__global__ void __launch_bounds__(128) k_gemm(const float* __restrict__ Bmat,
                                              const float* __restrict__ bias,
                                              float* __restrict__ out) {
    __shared__ float As[8][128];
    __shared__ float Bs[8][64];
    int t   = threadIdx.x;
    int bn0 = blockIdx.x * 64;    // column tiles fastest -> H strip L2-shared
    int bm0 = blockIdx.y * 128;

    // A staging: thread t loads row (bm0+t), 8 consecutive k
    int  arow   = bm0 + t;
    bool avalid = arow < NN;
    const float* aptr = g_H + (size_t)(avalid ? arow : 0) * KK;
    // B staging: thread t loads row t/16 (0..7), 4 cols at (t%16)*4
    int brow = t >> 4;
    int bcol = (t & 15) * 4;
    const float* bptr = Bmat + brow*OUTD + bn0 + bcol;

    int ty = t >> 3, tx = t & 7;   // 16x8 thread grid -> rows ty*8.., cols tx*8..

    float acc[8][8];
#pragma unroll
    for (int i = 0; i < 8; i++)
#pragma unroll
        for (int j = 0; j < 8; j++) acc[i][j] = 0.f;

    float4 ra0, ra1, rb;
    // prefetch kt = 0
    {
        if (avalid) { ra0 = *(const float4*)(aptr + 0); ra1 = *(const float4*)(aptr + 4); }
        else        { ra0 = make_float4(0,0,0,0); ra1 = ra0; }
        rb = *(const float4*)(bptr + 0);
    }

    const int KT = KK / 8;  // 300
    for (int kt = 0; kt < KT; kt++) {
        __syncthreads();
        As[0][t] = ra0.x; As[1][t] = ra0.y; As[2][t] = ra0.z; As[3][t] = ra0.w;
        As[4][t] = ra1.x; As[5][t] = ra1.y; As[6][t] = ra1.z; As[7][t] = ra1.w;
        *(float4*)&Bs[brow][bcol] = rb;
        __syncthreads();

        if (kt + 1 < KT) {
            int k0 = (kt + 1) * 8;
            if (avalid) { ra0 = *(const float4*)(aptr + k0); ra1 = *(const float4*)(aptr + k0 + 4); }
            rb = *(const float4*)(bptr + (size_t)k0 * OUTD);
        }

#pragma unroll
        for (int k = 0; k < 8; k++) {
            float4 a0 = *(float4*)&As[k][ty*8];
            float4 a1 = *(float4*)&As[k][ty*8 + 4];
            float4 b0 = *(float4*)&Bs[k][tx*8];
            float4 b1 = *(float4*)&Bs[k][tx*8 + 4];
            float av[8] = {a0.x,a0.y,a0.z,a0.w,a1.x,a1.y,a1.z,a1.w};
            float bv[8] = {b0.x,b0.y,b0.z,b0.w,b1.x,b1.y,b1.z,b1.w};
#pragma unroll
            for (int i = 0; i < 8; i++)
#pragma unroll
                for (int j = 0; j < 8; j++)
                    acc[i][j] += av[i] * bv[j];
        }
    }

    // epilogue: + bias, guarded rows
    float bb[8];
#pragma unroll
    for (int j = 0; j < 8; j++) bb[j] = bias[bn0 + tx*8 + j];
#pragma unroll
    for (int i = 0; i < 8; i++) {
        int row = bm0 + ty*8 + i;
        if (row < NN) {
            float4 o0 = make_float4(acc[i][0]+bb[0], acc[i][1]+bb[1], acc[i][2]+bb[2], acc[i][3]+bb[3]);
            float4 o1 = make_float4(acc[i][4]+bb[4], acc[i][5]+bb[5], acc[i][6]+bb[6], acc[i][7]+bb[7]);
            *(float4*)&out[(size_t)row*OUTD + bn0 + tx*8]     = o0;
            *(float4*)&out[(size_t)row*OUTD + bn0 + tx*8 + 4] = o1;
        }
    }
}

static inline int cdiv(int a, int b) { return (a + b - 1) / b; }

extern "C" void kernel_launch(void* const* d_in, const int* in_sizes, int n_in,
                              void* d_out, int out_size) {
    const float* features = (const float*)d_in[0];   // [N, 300]
    const float* comps    = (const float*)d_in[1];   // [R, B]
    const float* bases    = (const float*)d_in[2];   // [B, 300, 256] == basesFlat [2400, 256]
    const float* bias     = (const float*)d_in[3];   // [256]
    const int*   esrc     = (const int*)d_in[4];
    const int*   erel     = (const int*)d_in[5];
    const int*   edst     = (const int*)d_in[6];
    int E = in_sizes[4];

    k_zero<<<256, 256>>>();
    k_count<<<cdiv(E, 256), 256>>>(esrc, erel, E);
    k_scan<<<1, 1024>>>();
    k_scatter<<<cdiv(E, 256), 256>>>(esrc, erel, edst, E);
    k_gather<<<NN, 256>>>(features, comps);
    dim3 grid(OUTD / 64, cdiv(NN, 128));   // col tiles fastest for L2 reuse of H
    k_gemm<<<grid, 128>>>(bases, bias, (float*)d_out);
}

// round 3
// speedup vs baseline: 1.9653x; 1.9653x over previous
#include <cuda_runtime.h>
#include <stdint.h>

// Problem constants (fixed by reference)
#define NN   20000
#define RR   11
#define BB   8
#define IND  300
#define OUTD 256
#define EE   640000
#define KK   (BB*IND)           // 2400

// -------- device scratch (no dynamic allocation allowed) --------
__device__ int   g_deg[RR*NN];
__device__ int   g_cnt[NN];
__device__ int   g_off[NN+1];
__device__ int   g_cur[NN];
__device__ uint2 g_edges[EE];
__device__ float g_H[(size_t)NN*KK];   // 192 MB, tf32-rounded
__device__ float g_Bt[OUTD*KK];        // [256, 2400] K-major, tf32-rounded

// ================= helpers =================
__device__ __forceinline__ uint32_t smem_u32(const void* p){
    uint32_t a;
    asm("{ .reg .u64 t; cvta.to.shared.u64 t, %1; cvt.u32.u64 %0, t; }":"=r"(a):"l"(p));
    return a;
}
__device__ __forceinline__ float to_tf32(float x){
    uint32_t r;
    asm("cvt.rna.tf32.f32 %0, %1;" : "=r"(r) : "f"(x));
    return __uint_as_float(r);
}
__device__ __forceinline__ void cp16(uint32_t dst, const float* src, int sz){
    asm volatile("cp.async.cg.shared.global [%0], [%1], 16, %2;\n"
                 ::"r"(dst),"l"(src),"r"(sz));
}
__device__ __forceinline__ void mma_tf32_16x8x8(float* d, const uint32_t* a, const uint32_t* b){
    asm volatile(
        "mma.sync.aligned.m16n8k8.row.col.f32.tf32.tf32.f32 "
        "{%0,%1,%2,%3}, {%4,%5,%6,%7}, {%8,%9}, {%0,%1,%2,%3};"
        : "+f"(d[0]), "+f"(d[1]), "+f"(d[2]), "+f"(d[3])
        : "r"(a[0]), "r"(a[1]), "r"(a[2]), "r"(a[3]), "r"(b[0]), "r"(b[1]));
}

// -------- 0: reset counters --------
__global__ void k_zero() {
    int i  = blockIdx.x * blockDim.x + threadIdx.x;
    int st = gridDim.x * blockDim.x;
    for (int j = i; j < RR*NN; j += st) g_deg[j] = 0;
    for (int j = i; j < NN;    j += st) g_cnt[j] = 0;
}
// -------- 1: histogram degrees --------
__global__ void k_count(const int* __restrict__ src, const int* __restrict__ rel, int E) {
    int e = blockIdx.x * blockDim.x + threadIdx.x;
    if (e < E) {
        int s = src[e], r = rel[e];
        atomicAdd(&g_deg[r*NN + s], 1);
        atomicAdd(&g_cnt[s], 1);
    }
}
// -------- 2: exclusive scan (single block) --------
__global__ void k_scan() {
    __shared__ int sh[1024];
    int t = threadIdx.x;
    const int C = (NN + 1023) / 1024;
    int base = t * C;
    int sum = 0;
    for (int j = 0; j < C; j++) { int idx = base + j; if (idx < NN) sum += g_cnt[idx]; }
    sh[t] = sum; __syncthreads();
    for (int d = 1; d < 1024; d <<= 1) {
        int v = (t >= d) ? sh[t-d] : 0;
        __syncthreads();
        sh[t] += v;
        __syncthreads();
    }
    int run = (t > 0) ? sh[t-1] : 0;
    for (int j = 0; j < C; j++) {
        int idx = base + j;
        if (idx < NN) { g_off[idx] = run; g_cur[idx] = run; run += g_cnt[idx]; }
    }
    if (t == 1023) g_off[NN] = sh[1023];
}
// -------- 3: scatter edges into CSR, fold in 1/deg --------
__global__ void k_scatter(const int* __restrict__ src, const int* __restrict__ rel,
                          const int* __restrict__ dst, int E) {
    int e = blockIdx.x * blockDim.x + threadIdx.x;
    if (e < E) {
        int s = src[e], r = rel[e], d = dst[e];
        int pos = atomicAdd(&g_cur[s], 1);
        float val = 1.0f / (float)g_deg[r*NN + s];
        g_edges[pos] = make_uint2((unsigned)(d | (r << 16)), __float_as_uint(val));
    }
}
// -------- 4: per-node gather into basis space: H[n, b*300+i] (tf32-rounded) --------
__global__ void __launch_bounds__(256) k_gather(const float* __restrict__ feat,
                                                const float* __restrict__ comps) {
    __shared__ float s_comps[RR*BB];
    __shared__ uint2 s_ent[64];
    int n = blockIdx.x, t = threadIdx.x;
    if (t < RR*BB) s_comps[t] = comps[t];
    int beg = g_off[n], end = g_off[n+1];
    bool has2 = (t + 256) < IND;
    float a0[BB], a1[BB];
#pragma unroll
    for (int b = 0; b < BB; b++) { a0[b] = 0.f; a1[b] = 0.f; }
    __syncthreads();

    for (int base = beg; base < end; base += 64) {
        int m = min(64, end - base);
        if (t < m) s_ent[t] = g_edges[base + t];
        __syncthreads();
        for (int j = 0; j < m; j++) {
            uint2 ent = s_ent[j];
            int d = ent.x & 0xFFFF;
            int r = ent.x >> 16;
            float val = __uint_as_float(ent.y);
            const float* f = feat + (size_t)d * IND;
            float f0 = f[t];
            float f1 = has2 ? f[t + 256] : 0.f;
            const float* cp = &s_comps[r*BB];
#pragma unroll
            for (int b = 0; b < BB; b++) {
                float c = val * cp[b];
                a0[b] += c * f0;
                a1[b] += c * f1;
            }
        }
        __syncthreads();
    }

    float* h = g_H + (size_t)n * KK;
#pragma unroll
    for (int b = 0; b < BB; b++) {
        h[b*IND + t] = to_tf32(a0[b]);
        if (has2) h[b*IND + 256 + t] = to_tf32(a1[b]);
    }
}

// -------- 4.5: transpose bases [2400,256] -> g_Bt [256,2400] (tf32-rounded) --------
__global__ void k_transpose(const float* __restrict__ B) {
    __shared__ float tile[32][33];
    int bx = blockIdx.x * 32;   // k
    int by = blockIdx.y * 32;   // n
    int x = threadIdx.x, y = threadIdx.y;
    for (int j = y; j < 32; j += 8)
        tile[j][x] = B[(size_t)(bx + j) * OUTD + by + x];
    __syncthreads();
    for (int j = y; j < 32; j += 8)
        g_Bt[(size_t)(by + j) * KK + bx + x] = to_tf32(tile[x][j]);
}

// -------- 5: tf32 mma.sync GEMM: out[20000,256] = H @ basesFlat + bias --------
#define GBM 128
#define GBN 128
#define GBK 16
#define GSTG 4
#define GTH 256
#define AROWSTRIDE 20                 // floats, padded (conflict-free frag loads)
#define STAGE_BYTES (GBM*AROWSTRIDE*4)   // 10240 per operand per stage
#define SM_B_OFF (GSTG*STAGE_BYTES)      // 40960
#define GSMEM (2*GSTG*STAGE_BYTES)       // 81920

__global__ void __launch_bounds__(GTH, 2) k_gemm_mma(const float* __restrict__ bias,
                                                     float* __restrict__ out) {
    extern __shared__ char smem[];
    uint32_t sb = smem_u32(smem);
    int tid  = threadIdx.x;
    int lane = tid & 31, warp = tid >> 5;
    int g  = lane >> 2, tg = lane & 3;
    int wm = (warp >> 1) * 32, wn = (warp & 1) * 64;
    int bm0 = blockIdx.y * GBM, bn0 = blockIdx.x * GBN;

    // per-thread copy plan: 2 float4 for A, 2 float4 for B per stage
    int crow = tid >> 2;                 // 0..63
    int ckc  = (tid & 3) * 4;            // 0,4,8,12
    const float* aSrc0 = g_H + (size_t)min(bm0 + crow,      NN-1) * KK + ckc;
    const float* aSrc1 = g_H + (size_t)min(bm0 + crow + 64, NN-1) * KK + ckc;
    int aSz0 = (bm0 + crow      < NN) ? 16 : 0;
    int aSz1 = (bm0 + crow + 64 < NN) ? 16 : 0;
    const float* bSrc0 = g_Bt + (size_t)(bn0 + crow)      * KK + ckc;
    const float* bSrc1 = g_Bt + (size_t)(bn0 + crow + 64) * KK + ckc;
    uint32_t aDst0 = ( crow       * AROWSTRIDE + ckc) * 4;
    uint32_t aDst1 = ((crow + 64) * AROWSTRIDE + ckc) * 4;

#define ISSUE_STAGE(kt, s) do { \
        uint32_t aB = sb + (s) * STAGE_BYTES; \
        uint32_t bB = sb + SM_B_OFF + (s) * STAGE_BYTES; \
        size_t ko = (size_t)(kt) * GBK; \
        cp16(aB + aDst0, aSrc0 + ko, aSz0); \
        cp16(aB + aDst1, aSrc1 + ko, aSz1); \
        cp16(bB + aDst0, bSrc0 + ko, 16); \
        cp16(bB + aDst1, bSrc1 + ko, 16); \
        asm volatile("cp.async.commit_group;":::"memory"); \
    } while (0)

    float acc[2][8][4];
#pragma unroll
    for (int mi = 0; mi < 2; mi++)
#pragma unroll
        for (int ni = 0; ni < 8; ni++)
#pragma unroll
            for (int j = 0; j < 4; j++) acc[mi][ni][j] = 0.f;

    ISSUE_STAGE(0, 0);
    ISSUE_STAGE(1, 1);
    ISSUE_STAGE(2, 2);

    const int KT = KK / GBK;  // 150
    for (int kt = 0; kt < KT; kt++) {
        int s = kt & (GSTG - 1);
        asm volatile("cp.async.wait_group %0;" :: "n"(GSTG - 2) : "memory");
        __syncthreads();
        if (kt + 3 < KT) ISSUE_STAGE(kt + 3, (kt + 3) & (GSTG - 1));
        else asm volatile("cp.async.commit_group;":::"memory");

        const float* As = (const float*)(smem + s * STAGE_BYTES);
        const float* Bs = (const float*)(smem + SM_B_OFF + s * STAGE_BYTES);
#pragma unroll
        for (int kk = 0; kk < GBK; kk += 8) {
            uint32_t a[2][4], b[8][2];
#pragma unroll
            for (int mi = 0; mi < 2; mi++) {
                int mb = wm + mi * 16;
                a[mi][0] = __float_as_uint(As[(mb + g)     * AROWSTRIDE + kk + tg]);
                a[mi][1] = __float_as_uint(As[(mb + g + 8) * AROWSTRIDE + kk + tg]);
                a[mi][2] = __float_as_uint(As[(mb + g)     * AROWSTRIDE + kk + tg + 4]);
                a[mi][3] = __float_as_uint(As[(mb + g + 8) * AROWSTRIDE + kk + tg + 4]);
            }
#pragma unroll
            for (int ni = 0; ni < 8; ni++) {
                int nb = wn + ni * 8;
                b[ni][0] = __float_as_uint(Bs[(nb + g) * AROWSTRIDE + kk + tg]);
                b[ni][1] = __float_as_uint(Bs[(nb + g) * AROWSTRIDE + kk + tg + 4]);
            }
#pragma unroll
            for (int mi = 0; mi < 2; mi++)
#pragma unroll
                for (int ni = 0; ni < 8; ni++)
                    mma_tf32_16x8x8(acc[mi][ni], a[mi], b[ni]);
        }
    }

    // epilogue: + bias
#pragma unroll
    for (int mi = 0; mi < 2; mi++) {
        int row0 = bm0 + wm + mi * 16 + g;
#pragma unroll
        for (int ni = 0; ni < 8; ni++) {
            int col = bn0 + wn + ni * 8 + tg * 2;
            float b0 = bias[col], b1 = bias[col + 1];
            if (row0 < NN) {
                float2 v = make_float2(acc[mi][ni][0] + b0, acc[mi][ni][1] + b1);
                *(float2*)&out[(size_t)row0 * OUTD + col] = v;
            }
            if (row0 + 8 < NN) {
                float2 v = make_float2(acc[mi][ni][2] + b0, acc[mi][ni][3] + b1);
                *(float2*)&out[(size_t)(row0 + 8) * OUTD + col] = v;
            }
        }
    }
}

static inline int cdiv(int a, int b) { return (a + b - 1) / b; }

extern "C" void kernel_launch(void* const* d_in, const int* in_sizes, int n_in,
                              void* d_out, int out_size) {
    const float* features = (const float*)d_in[0];
    const float* comps    = (const float*)d_in[1];
    const float* bases    = (const float*)d_in[2];   // flat [2400, 256]
    const float* bias     = (const float*)d_in[3];
    const int*   esrc     = (const int*)d_in[4];
    const int*   erel     = (const int*)d_in[5];
    const int*   edst     = (const int*)d_in[6];
    int E = in_sizes[4];

    cudaFuncSetAttribute(k_gemm_mma, cudaFuncAttributeMaxDynamicSharedMemorySize, GSMEM);

    k_zero<<<256, 256>>>();
    k_count<<<cdiv(E, 256), 256>>>(esrc, erel, E);
    k_scan<<<1, 1024>>>();
    k_scatter<<<cdiv(E, 256), 256>>>(esrc, erel, edst, E);
    dim3 tgrid(KK/32, OUTD/32), tblk(32, 8);
    k_transpose<<<tgrid, tblk>>>(bases);
    k_gather<<<NN, 256>>>(features, comps);
    dim3 ggrid(OUTD / GBN, cdiv(NN, GBM));
    k_gemm_mma<<<ggrid, GTH, GSMEM>>>(bias, (float*)d_out);
}

// round 4
// speedup vs baseline: 2.4046x; 1.2235x over previous
#include <cuda_runtime.h>
#include <cuda_fp16.h>
#include <stdint.h>

// Problem constants (fixed by reference)
#define NN   20000
#define RR   11
#define BB   8
#define IND  300
#define OUTD 256
#define EE   640000
#define KK   (BB*IND)           // 2400

// -------- device scratch (no dynamic allocation allowed) --------
__device__ int    g_deg[RR*NN];
__device__ int    g_cnt[NN];
__device__ int    g_off[NN+1];
__device__ int    g_cur[NN];
__device__ uint2  g_edges[EE];
__device__ __half g_H[(size_t)NN*KK];   // 96 MB, fp16
__device__ __half g_Bt[OUTD*KK];        // [256, 2400] K-major, fp16

// ================= helpers =================
__device__ __forceinline__ void cp16(uint32_t dst, const void* src, int sz){
    asm volatile("cp.async.cg.shared.global [%0], [%1], 16, %2;\n"
                 ::"r"(dst),"l"(src),"r"(sz));
}
__device__ __forceinline__ uint32_t smem_u32(const void* p){
    uint32_t a;
    asm("{ .reg .u64 t; cvta.to.shared.u64 t, %1; cvt.u32.u64 %0, t; }":"=r"(a):"l"(p));
    return a;
}
__device__ __forceinline__ void mma_f16_16x8x16(float* d, const uint32_t* a, const uint32_t* b){
    asm volatile(
        "mma.sync.aligned.m16n8k16.row.col.f32.f16.f16.f32 "
        "{%0,%1,%2,%3}, {%4,%5,%6,%7}, {%8,%9}, {%0,%1,%2,%3};"
        : "+f"(d[0]), "+f"(d[1]), "+f"(d[2]), "+f"(d[3])
        : "r"(a[0]), "r"(a[1]), "r"(a[2]), "r"(a[3]), "r"(b[0]), "r"(b[1]));
}

// -------- 0: reset counters --------
__global__ void k_zero() {
    int i  = blockIdx.x * blockDim.x + threadIdx.x;
    int st = gridDim.x * blockDim.x;
    for (int j = i; j < RR*NN; j += st) g_deg[j] = 0;
    for (int j = i; j < NN;    j += st) g_cnt[j] = 0;
}
// -------- 1: histogram degrees --------
__global__ void k_count(const int* __restrict__ src, const int* __restrict__ rel, int E) {
    int e = blockIdx.x * blockDim.x + threadIdx.x;
    if (e < E) {
        int s = src[e], r = rel[e];
        atomicAdd(&g_deg[r*NN + s], 1);
        atomicAdd(&g_cnt[s], 1);
    }
}
// -------- 2: exclusive scan (single block) --------
__global__ void k_scan() {
    __shared__ int sh[1024];
    int t = threadIdx.x;
    const int C = (NN + 1023) / 1024;
    int base = t * C;
    int sum = 0;
    for (int j = 0; j < C; j++) { int idx = base + j; if (idx < NN) sum += g_cnt[idx]; }
    sh[t] = sum; __syncthreads();
    for (int d = 1; d < 1024; d <<= 1) {
        int v = (t >= d) ? sh[t-d] : 0;
        __syncthreads();
        sh[t] += v;
        __syncthreads();
    }
    int run = (t > 0) ? sh[t-1] : 0;
    for (int j = 0; j < C; j++) {
        int idx = base + j;
        if (idx < NN) { g_off[idx] = run; g_cur[idx] = run; run += g_cnt[idx]; }
    }
    if (t == 1023) g_off[NN] = sh[1023];
}
// -------- 3: scatter edges into CSR, fold in 1/deg --------
__global__ void k_scatter(const int* __restrict__ src, const int* __restrict__ rel,
                          const int* __restrict__ dst, int E) {
    int e = blockIdx.x * blockDim.x + threadIdx.x;
    if (e < E) {
        int s = src[e], r = rel[e], d = dst[e];
        int pos = atomicAdd(&g_cur[s], 1);
        float val = 1.0f / (float)g_deg[r*NN + s];
        g_edges[pos] = make_uint2((unsigned)(d | (r << 16)), __float_as_uint(val));
    }
}
// -------- 4: per-node gather into basis space: H[n, b*300+i] (fp16 out) --------
__global__ void __launch_bounds__(256) k_gather(const float* __restrict__ feat,
                                                const float* __restrict__ comps) {
    __shared__ float s_comps[RR*BB];
    __shared__ uint2 s_ent[64];
    int n = blockIdx.x, t = threadIdx.x;
    if (t < RR*BB) s_comps[t] = comps[t];
    int beg = g_off[n], end = g_off[n+1];
    bool has2 = (t + 256) < IND;
    float a0[BB], a1[BB];
#pragma unroll
    for (int b = 0; b < BB; b++) { a0[b] = 0.f; a1[b] = 0.f; }
    __syncthreads();

    for (int base = beg; base < end; base += 64) {
        int m = min(64, end - base);
        if (t < m) s_ent[t] = g_edges[base + t];
        __syncthreads();
        for (int j = 0; j < m; j++) {
            uint2 ent = s_ent[j];
            int d = ent.x & 0xFFFF;
            int r = ent.x >> 16;
            float val = __uint_as_float(ent.y);
            const float* f = feat + (size_t)d * IND;
            float f0 = f[t];
            float f1 = has2 ? f[t + 256] : 0.f;
            const float* cp = &s_comps[r*BB];
#pragma unroll
            for (int b = 0; b < BB; b++) {
                float c = val * cp[b];
                a0[b] += c * f0;
                a1[b] += c * f1;
            }
        }
        __syncthreads();
    }

    __half* h = g_H + (size_t)n * KK;
#pragma unroll
    for (int b = 0; b < BB; b++) {
        h[b*IND + t] = __float2half_rn(a0[b]);
        if (has2) h[b*IND + 256 + t] = __float2half_rn(a1[b]);
    }
}

// -------- 4.5: transpose bases [2400,256] -> g_Bt [256,2400] (fp16) --------
__global__ void k_transpose(const float* __restrict__ B) {
    __shared__ float tile[32][33];
    int bx = blockIdx.x * 32;   // k
    int by = blockIdx.y * 32;   // n
    int x = threadIdx.x, y = threadIdx.y;
    for (int j = y; j < 32; j += 8)
        tile[j][x] = B[(size_t)(bx + j) * OUTD + by + x];
    __syncthreads();
    for (int j = y; j < 32; j += 8)
        g_Bt[(size_t)(by + j) * KK + bx + x] = __float2half_rn(tile[x][j]);
}

// -------- 5: fp16 mma.sync GEMM: out[20000,256] = H @ basesFlat + bias --------
#define GBM 128
#define GBN 128
#define GBK 32                     // halves per stage (2 k16 steps)
#define GSTG 4
#define GTH 256
#define SHALVES 40                 // smem row stride in halves (32 + 8 pad)
#define STAGE_BYTES (GBM*SHALVES*2)   // 10240 per operand per stage
#define SM_B_OFF (GSTG*STAGE_BYTES)   // 40960
#define GSMEM (2*GSTG*STAGE_BYTES)    // 81920

__global__ void __launch_bounds__(GTH, 2) k_gemm_mma(const float* __restrict__ bias,
                                                     float* __restrict__ out) {
    extern __shared__ char smem[];
    uint32_t sb = smem_u32(smem);
    int tid  = threadIdx.x;
    int lane = tid & 31, warp = tid >> 5;
    int g  = lane >> 2, tg = lane & 3;
    int wm = (warp >> 1) * 32, wn = (warp & 1) * 64;
    int bm0 = blockIdx.y * GBM, bn0 = blockIdx.x * GBN;

    // per-thread copy plan: 2 x 16B for A, 2 x 16B for B per stage
    int crow = tid >> 1;                 // 0..127
    int g40  = (tid & 1) * 2;            // granule 0 or 2 (and +1)
    const __half* aSrc = g_H  + (size_t)min(bm0 + crow, NN-1) * KK + g40 * 8;
    int aSz = (bm0 + crow < NN) ? 16 : 0;
    const __half* bSrc = g_Bt + (size_t)(bn0 + crow) * KK + g40 * 8;
    uint32_t dst0 = (crow * SHALVES + g40 * 8) * 2;       // bytes
    uint32_t dst1 = dst0 + 16;

#define ISSUE_STAGE(kt, s) do { \
        uint32_t aB = sb + (s) * STAGE_BYTES; \
        uint32_t bB = sb + SM_B_OFF + (s) * STAGE_BYTES; \
        size_t ko = (size_t)(kt) * GBK; \
        cp16(aB + dst0, aSrc + ko,     aSz); \
        cp16(aB + dst1, aSrc + ko + 8, aSz); \
        cp16(bB + dst0, bSrc + ko,     16); \
        cp16(bB + dst1, bSrc + ko + 8, 16); \
        asm volatile("cp.async.commit_group;":::"memory"); \
    } while (0)

    float acc[2][8][4];
#pragma unroll
    for (int mi = 0; mi < 2; mi++)
#pragma unroll
        for (int ni = 0; ni < 8; ni++)
#pragma unroll
            for (int j = 0; j < 4; j++) acc[mi][ni][j] = 0.f;

    ISSUE_STAGE(0, 0);
    ISSUE_STAGE(1, 1);
    ISSUE_STAGE(2, 2);

    const int KT = KK / GBK;  // 75
    for (int kt = 0; kt < KT; kt++) {
        int s = kt & (GSTG - 1);
        asm volatile("cp.async.wait_group %0;" :: "n"(GSTG - 2) : "memory");
        __syncthreads();
        if (kt + 3 < KT) ISSUE_STAGE(kt + 3, (kt + 3) & (GSTG - 1));
        else asm volatile("cp.async.commit_group;":::"memory");

        const __half* As = (const __half*)(smem + s * STAGE_BYTES);
        const __half* Bs = (const __half*)(smem + SM_B_OFF + s * STAGE_BYTES);
#pragma unroll
        for (int kk = 0; kk < GBK; kk += 16) {
            uint32_t a[2][4], b[8][2];
#pragma unroll
            for (int mi = 0; mi < 2; mi++) {
                int mb = wm + mi * 16;
                a[mi][0] = *(const uint32_t*)&As[(mb + g)     * SHALVES + kk + tg*2];
                a[mi][1] = *(const uint32_t*)&As[(mb + g + 8) * SHALVES + kk + tg*2];
                a[mi][2] = *(const uint32_t*)&As[(mb + g)     * SHALVES + kk + tg*2 + 8];
                a[mi][3] = *(const uint32_t*)&As[(mb + g + 8) * SHALVES + kk + tg*2 + 8];
            }
#pragma unroll
            for (int ni = 0; ni < 8; ni++) {
                int nb = wn + ni * 8;
                b[ni][0] = *(const uint32_t*)&Bs[(nb + g) * SHALVES + kk + tg*2];
                b[ni][1] = *(const uint32_t*)&Bs[(nb + g) * SHALVES + kk + tg*2 + 8];
            }
#pragma unroll
            for (int mi = 0; mi < 2; mi++)
#pragma unroll
                for (int ni = 0; ni < 8; ni++)
                    mma_f16_16x8x16(acc[mi][ni], a[mi], b[ni]);
        }
    }

    // epilogue: + bias
#pragma unroll
    for (int mi = 0; mi < 2; mi++) {
        int row0 = bm0 + wm + mi * 16 + g;
#pragma unroll
        for (int ni = 0; ni < 8; ni++) {
            int col = bn0 + wn + ni * 8 + tg * 2;
            float b0 = bias[col], b1 = bias[col + 1];
            if (row0 < NN) {
                float2 v = make_float2(acc[mi][ni][0] + b0, acc[mi][ni][1] + b1);
                *(float2*)&out[(size_t)row0 * OUTD + col] = v;
            }
            if (row0 + 8 < NN) {
                float2 v = make_float2(acc[mi][ni][2] + b0, acc[mi][ni][3] + b1);
                *(float2*)&out[(size_t)(row0 + 8) * OUTD + col] = v;
            }
        }
    }
}

static inline int cdiv(int a, int b) { return (a + b - 1) / b; }

extern "C" void kernel_launch(void* const* d_in, const int* in_sizes, int n_in,
                              void* d_out, int out_size) {
    const float* features = (const float*)d_in[0];
    const float* comps    = (const float*)d_in[1];
    const float* bases    = (const float*)d_in[2];   // flat [2400, 256]
    const float* bias     = (const float*)d_in[3];
    const int*   esrc     = (const int*)d_in[4];
    const int*   erel     = (const int*)d_in[5];
    const int*   edst     = (const int*)d_in[6];
    int E = in_sizes[4];

    cudaFuncSetAttribute(k_gemm_mma, cudaFuncAttributeMaxDynamicSharedMemorySize, GSMEM);

    k_zero<<<256, 256>>>();
    k_count<<<cdiv(E, 256), 256>>>(esrc, erel, E);
    k_scan<<<1, 1024>>>();
    k_scatter<<<cdiv(E, 256), 256>>>(esrc, erel, edst, E);
    dim3 tgrid(KK/32, OUTD/32), tblk(32, 8);
    k_transpose<<<tgrid, tblk>>>(bases);
    k_gather<<<NN, 256>>>(features, comps);
    dim3 ggrid(OUTD / GBN, cdiv(NN, GBM));
    k_gemm_mma<<<ggrid, GTH, GSMEM>>>(bias, (float*)d_out);
}

// round 5
// speedup vs baseline: 2.5031x; 1.0410x over previous
#include <cuda_runtime.h>
#include <cuda_fp16.h>
#include <stdint.h>

// Problem constants (fixed by reference)
#define NN   20000
#define RR   11
#define BB   8
#define IND  300
#define OUTD 256
#define EE   640000
#define KK   (BB*IND)           // 2400

// -------- device scratch (no dynamic allocation allowed) --------
__device__ int    g_deg[RR*NN];
__device__ int    g_cnt[NN];
__device__ int    g_off[NN+1];
__device__ int    g_cur[NN];
__device__ uint2  g_edges[EE];
__device__ __half g_H[(size_t)NN*KK];   // 96 MB, fp16
__device__ __half g_Bt[OUTD*KK];        // [256, 2400] K-major, fp16

// ================= helpers =================
__device__ __forceinline__ void cp16(uint32_t dst, const void* src, int sz){
    asm volatile("cp.async.cg.shared.global [%0], [%1], 16, %2;\n"
                 ::"r"(dst),"l"(src),"r"(sz));
}
__device__ __forceinline__ uint32_t smem_u32(const void* p){
    uint32_t a;
    asm("{ .reg .u64 t; cvta.to.shared.u64 t, %1; cvt.u32.u64 %0, t; }":"=r"(a):"l"(p));
    return a;
}
__device__ __forceinline__ void ldm_x4(uint32_t* r, uint32_t addr){
    asm volatile("ldmatrix.sync.aligned.m8n8.x4.shared.b16 {%0,%1,%2,%3}, [%4];"
        : "=r"(r[0]),"=r"(r[1]),"=r"(r[2]),"=r"(r[3]) : "r"(addr));
}
__device__ __forceinline__ void mma_f16_16x8x16(float* d, const uint32_t* a, const uint32_t* b){
    asm volatile(
        "mma.sync.aligned.m16n8k16.row.col.f32.f16.f16.f32 "
        "{%0,%1,%2,%3}, {%4,%5,%6,%7}, {%8,%9}, {%0,%1,%2,%3};"
        : "+f"(d[0]), "+f"(d[1]), "+f"(d[2]), "+f"(d[3])
        : "r"(a[0]), "r"(a[1]), "r"(a[2]), "r"(a[3]), "r"(b[0]), "r"(b[1]));
}

// -------- 0: reset counters --------
__global__ void k_zero() {
    int i  = blockIdx.x * blockDim.x + threadIdx.x;
    int st = gridDim.x * blockDim.x;
    for (int j = i; j < RR*NN; j += st) g_deg[j] = 0;
    for (int j = i; j < NN;    j += st) g_cnt[j] = 0;
}
// -------- 1: histogram degrees --------
__global__ void k_count(const int* __restrict__ src, const int* __restrict__ rel, int E) {
    int e = blockIdx.x * blockDim.x + threadIdx.x;
    if (e < E) {
        int s = src[e], r = rel[e];
        atomicAdd(&g_deg[r*NN + s], 1);
        atomicAdd(&g_cnt[s], 1);
    }
}
// -------- 2: exclusive scan (single block) --------
__global__ void k_scan() {
    __shared__ int sh[1024];
    int t = threadIdx.x;
    const int C = (NN + 1023) / 1024;
    int base = t * C;
    int sum = 0;
    for (int j = 0; j < C; j++) { int idx = base + j; if (idx < NN) sum += g_cnt[idx]; }
    sh[t] = sum; __syncthreads();
    for (int d = 1; d < 1024; d <<= 1) {
        int v = (t >= d) ? sh[t-d] : 0;
        __syncthreads();
        sh[t] += v;
        __syncthreads();
    }
    int run = (t > 0) ? sh[t-1] : 0;
    for (int j = 0; j < C; j++) {
        int idx = base + j;
        if (idx < NN) { g_off[idx] = run; g_cur[idx] = run; run += g_cnt[idx]; }
    }
    if (t == 1023) g_off[NN] = sh[1023];
}
// -------- 3: scatter edges into CSR, fold in 1/deg --------
__global__ void k_scatter(const int* __restrict__ src, const int* __restrict__ rel,
                          const int* __restrict__ dst, int E) {
    int e = blockIdx.x * blockDim.x + threadIdx.x;
    if (e < E) {
        int s = src[e], r = rel[e], d = dst[e];
        int pos = atomicAdd(&g_cur[s], 1);
        float val = 1.0f / (float)g_deg[r*NN + s];
        g_edges[pos] = make_uint2((unsigned)(d | (r << 16)), __float_as_uint(val));
    }
}
// -------- 4: per-node gather into basis space: H[n, b*300+i] (fp16 out) --------
__global__ void __launch_bounds__(256) k_gather(const float* __restrict__ feat,
                                                const float* __restrict__ comps) {
    __shared__ float s_comps[RR*BB];
    __shared__ uint2 s_ent[64];
    int n = blockIdx.x, t = threadIdx.x;
    if (t < RR*BB) s_comps[t] = comps[t];
    int beg = g_off[n], end = g_off[n+1];
    bool has2 = (t + 256) < IND;
    float a0[BB], a1[BB];
#pragma unroll
    for (int b = 0; b < BB; b++) { a0[b] = 0.f; a1[b] = 0.f; }
    __syncthreads();

    for (int base = beg; base < end; base += 64) {
        int m = min(64, end - base);
        if (t < m) s_ent[t] = g_edges[base + t];
        __syncthreads();
        int j = 0;
#pragma unroll 1
        for (; j + 2 <= m; j += 2) {
            uint2 e0 = s_ent[j], e1 = s_ent[j+1];
            const float* fa = feat + (size_t)(e0.x & 0xFFFF) * IND;
            const float* fb = feat + (size_t)(e1.x & 0xFFFF) * IND;
            float va = __uint_as_float(e0.y), vb = __uint_as_float(e1.y);
            // issue all 4 loads up front (MLP=4)
            float fa0 = fa[t];
            float fb0 = fb[t];
            float fa1 = has2 ? fa[t + 256] : 0.f;
            float fb1 = has2 ? fb[t + 256] : 0.f;
            const float* ca = &s_comps[(e0.x >> 16) * BB];
            const float* cb = &s_comps[(e1.x >> 16) * BB];
#pragma unroll
            for (int b = 0; b < BB; b++) {
                float c0 = va * ca[b];
                float c1 = vb * cb[b];
                a0[b] += c0 * fa0; a1[b] += c0 * fa1;
                a0[b] += c1 * fb0; a1[b] += c1 * fb1;
            }
        }
        if (j < m) {
            uint2 e0 = s_ent[j];
            const float* fa = feat + (size_t)(e0.x & 0xFFFF) * IND;
            float va = __uint_as_float(e0.y);
            float fa0 = fa[t];
            float fa1 = has2 ? fa[t + 256] : 0.f;
            const float* ca = &s_comps[(e0.x >> 16) * BB];
#pragma unroll
            for (int b = 0; b < BB; b++) {
                float c0 = va * ca[b];
                a0[b] += c0 * fa0; a1[b] += c0 * fa1;
            }
        }
        __syncthreads();
    }

    __half* h = g_H + (size_t)n * KK;
#pragma unroll
    for (int b = 0; b < BB; b++) {
        h[b*IND + t] = __float2half_rn(a0[b]);
        if (has2) h[b*IND + 256 + t] = __float2half_rn(a1[b]);
    }
}

// -------- 4.5: transpose bases [2400,256] -> g_Bt [256,2400] (fp16) --------
__global__ void k_transpose(const float* __restrict__ B) {
    __shared__ float tile[32][33];
    int bx = blockIdx.x * 32;   // k
    int by = blockIdx.y * 32;   // n
    int x = threadIdx.x, y = threadIdx.y;
    for (int j = y; j < 32; j += 8)
        tile[j][x] = B[(size_t)(bx + j) * OUTD + by + x];
    __syncthreads();
    for (int j = y; j < 32; j += 8)
        g_Bt[(size_t)(by + j) * KK + bx + x] = __float2half_rn(tile[x][j]);
}

// -------- 5: fp16 mma.sync + ldmatrix GEMM: out = H @ basesFlat + bias --------
// BM=64, BN=256 (single column pass), 256 thr = 8 warps (2x4), warp tile 32x64.
#define GBM 64
#define GBK 32                       // halves per stage (2 x k16)
#define GSTG 4
#define GTH 256
#define SHV 40                       // smem row stride in halves
#define STG_A (GBM*SHV*2)            // 5120 B
#define STG_B (OUTD*SHV*2)           // 20480 B
#define STG_ALL (STG_A+STG_B)        // 25600 B
#define GSMEM (GSTG*STG_ALL)         // 102400 B

__global__ void __launch_bounds__(GTH, 2) k_gemm_mma(const float* __restrict__ bias,
                                                     float* __restrict__ out) {
    extern __shared__ char smem[];
    uint32_t sb = smem_u32(smem);
    int tid  = threadIdx.x;
    int lane = tid & 31, warp = tid >> 5;
    int g  = lane >> 2, tg = lane & 3;
    int wm = (warp >> 2) * 32;        // 0 or 32
    int wn = (warp & 3) * 64;         // 0,64,128,192
    int bm0 = blockIdx.x * GBM;

    // ---- cp.async plan: A 256 chunks (1/thr), B 1024 chunks (4/thr) ----
    int arow = tid >> 2, q = tid & 3;                  // A: row 0..63, granule 0..3
    const __half* aSrc = g_H + (size_t)min(bm0 + arow, NN-1) * KK + q * 8;
    int aSz = (bm0 + arow < NN) ? 16 : 0;
    uint32_t aDst = (uint32_t)(arow * SHV + q * 8) * 2;
    const __half* bSrc[4]; uint32_t bDst[4];
#pragma unroll
    for (int i = 0; i < 4; i++) {
        int brow = (tid >> 2) + i * 64;                // 0..255
        bSrc[i] = g_Bt + (size_t)brow * KK + q * 8;
        bDst[i] = (uint32_t)(brow * SHV + q * 8) * 2;
    }

#define ISSUE_STAGE(kt, s) do { \
        uint32_t base = sb + (s) * STG_ALL; \
        size_t ko = (size_t)(kt) * GBK; \
        cp16(base + aDst, aSrc + ko, aSz); \
        _Pragma("unroll") for (int i = 0; i < 4; i++) \
            cp16(base + STG_A + bDst[i], bSrc[i] + ko, 16); \
        asm volatile("cp.async.commit_group;":::"memory"); \
    } while (0)

    // ---- ldmatrix lane offsets (in halves, relative to stage A/B base) ----
    int sel = lane >> 3, l8 = lane & 7;
    uint32_t aOff[2], bOff[4];
#pragma unroll
    for (int mi = 0; mi < 2; mi++)
        aOff[mi] = (uint32_t)((wm + mi*16 + (sel & 1)*8 + l8) * SHV + (sel >> 1)*8) * 2;
#pragma unroll
    for (int p = 0; p < 4; p++)
        bOff[p] = (uint32_t)((wn + p*16 + (sel >> 1)*8 + l8) * SHV + (sel & 1)*8) * 2;

    float acc[2][8][4];
#pragma unroll
    for (int mi = 0; mi < 2; mi++)
#pragma unroll
        for (int ni = 0; ni < 8; ni++)
#pragma unroll
            for (int j = 0; j < 4; j++) acc[mi][ni][j] = 0.f;

    ISSUE_STAGE(0, 0);
    ISSUE_STAGE(1, 1);
    ISSUE_STAGE(2, 2);

    const int KT = KK / GBK;  // 75
    for (int kt = 0; kt < KT; kt++) {
        int s = kt & (GSTG - 1);
        asm volatile("cp.async.wait_group %0;" :: "n"(GSTG - 2) : "memory");
        __syncthreads();
        if (kt + 3 < KT) ISSUE_STAGE(kt + 3, (kt + 3) & (GSTG - 1));
        else asm volatile("cp.async.commit_group;":::"memory");

        uint32_t baseA = sb + s * STG_ALL;
        uint32_t baseB = baseA + STG_A;
#pragma unroll
        for (int kk = 0; kk < GBK; kk += 16) {
            uint32_t a[2][4], b[8][2];
#pragma unroll
            for (int mi = 0; mi < 2; mi++)
                ldm_x4(a[mi], baseA + aOff[mi] + kk*2);
#pragma unroll
            for (int p = 0; p < 4; p++) {
                uint32_t r[4];
                ldm_x4(r, baseB + bOff[p] + kk*2);
                b[2*p][0] = r[0]; b[2*p][1] = r[1];
                b[2*p+1][0] = r[2]; b[2*p+1][1] = r[3];
            }
#pragma unroll
            for (int mi = 0; mi < 2; mi++)
#pragma unroll
                for (int ni = 0; ni < 8; ni++)
                    mma_f16_16x8x16(acc[mi][ni], a[mi], b[ni]);
        }
    }

    // epilogue: + bias
#pragma unroll
    for (int mi = 0; mi < 2; mi++) {
        int row0 = bm0 + wm + mi * 16 + g;
#pragma unroll
        for (int ni = 0; ni < 8; ni++) {
            int col = wn + ni * 8 + tg * 2;
            float b0 = bias[col], b1 = bias[col + 1];
            if (row0 < NN) {
                float2 v = make_float2(acc[mi][ni][0] + b0, acc[mi][ni][1] + b1);
                *(float2*)&out[(size_t)row0 * OUTD + col] = v;
            }
            if (row0 + 8 < NN) {
                float2 v = make_float2(acc[mi][ni][2] + b0, acc[mi][ni][3] + b1);
                *(float2*)&out[(size_t)(row0 + 8) * OUTD + col] = v;
            }
        }
    }
}

static inline int cdiv(int a, int b) { return (a + b - 1) / b; }

extern "C" void kernel_launch(void* const* d_in, const int* in_sizes, int n_in,
                              void* d_out, int out_size) {
    const float* features = (const float*)d_in[0];
    const float* comps    = (const float*)d_in[1];
    const float* bases    = (const float*)d_in[2];   // flat [2400, 256]
    const float* bias     = (const float*)d_in[3];
    const int*   esrc     = (const int*)d_in[4];
    const int*   erel     = (const int*)d_in[5];
    const int*   edst     = (const int*)d_in[6];
    int E = in_sizes[4];

    cudaFuncSetAttribute(k_gemm_mma, cudaFuncAttributeMaxDynamicSharedMemorySize, GSMEM);

    k_zero<<<256, 256>>>();
    k_count<<<cdiv(E, 256), 256>>>(esrc, erel, E);
    k_scan<<<1, 1024>>>();
    k_scatter<<<cdiv(E, 256), 256>>>(esrc, erel, edst, E);
    dim3 tgrid(KK/32, OUTD/32), tblk(32, 8);
    k_transpose<<<tgrid, tblk>>>(bases);
    k_gather<<<NN, 256>>>(features, comps);
    k_gemm_mma<<<cdiv(NN, GBM), GTH, GSMEM>>>(bias, (float*)d_out);
}